// round 16
// baseline (speedup 1.0000x reference)
#include <cuda_runtime.h>
#include <math.h>

typedef unsigned long long ull;

// Problem constants
#define BATCH 64
#define L0 128
#define C0 16
#define KW 5
#define C1 128
#define C2 1024
#define L2N 120
#define C3 8192
#define L3 116
#define AD 2

// k_back decomposition: unit = (tblk, g8) owned by ONE warp.
// lane = (group-local gl = lane>>2 in [0,8), filter-pair fp = lane&3)
#define TT 4
#define NTBLK (L3 / TT)          // 29
#define NG8 (C2 / 8)             // 128
#define NU (NTBLK * NG8)         // 3712 units
#define BPT 8                    // batches per task
#define NTASK (NU * (BATCH/BPT)) // 29696
#define GRID_BACK 444            // 3 CTAs/SM resident
#define NWARPS (GRID_BACK * 8)   // 3552
#define TPW (NTASK / NWARPS)     // 8
#define TREM (NTASK % NWARPS)    // 1280

// k_front tiling
#define FROWS 8                  // y2 rows per CTA
#define FY1 (FROWS + KW - 1)     // 12 y1 rows

// Scratch (device globals; no allocation)
__device__ float g_y2[(size_t)BATCH * L2N * C2];        // ~31.5 MB (L2-resident)
__device__ float g_part2[(size_t)BATCH * NU * 8 * AD];  // 15.2 MB partials

// ---- f32x2 packed helpers ---------------------------------------------------
__device__ __forceinline__ ull ffma2(ull a, ull b, ull c) {
    ull d;
    asm("fma.rn.f32x2 %0, %1, %2, %3;" : "=l"(d) : "l"(a), "l"(b), "l"(c));
    return d;
}
__device__ __forceinline__ ull add2(ull a, ull b) {
    ull d;
    asm("add.rn.f32x2 %0, %1, %2;" : "=l"(d) : "l"(a), "l"(b));
    return d;
}
__device__ __forceinline__ ull pack2(float lo, float hi) {
    ull d;
    asm("mov.b64 %0, {%1, %2};" : "=l"(d) : "f"(lo), "f"(hi));
    return d;
}
__device__ __forceinline__ void unpack2(ull v, float& lo, float& hi) {
    asm("mov.b64 {%0, %1}, %2;" : "=f"(lo), "=f"(hi) : "l"(v));
}
// Single-block relu: internal movs to dead temps are coalescable by ptxas,
// ideal codegen = 2x FMNMX on the pair halves in place.
__device__ __forceinline__ ull relu2(ull v) {
    asm("{\n\t"
        ".reg .f32 lo, hi;\n\t"
        "mov.b64 {lo, hi}, %0;\n\t"
        "max.f32 lo, lo, 0f00000000;\n\t"
        "max.f32 hi, hi, 0f00000000;\n\t"
        "mov.b64 %0, {lo, hi};\n\t"
        "}" : "+l"(v));
    return v;
}
// Single-block horizontal add: ideal codegen = 1 FADD.
__device__ __forceinline__ float hadd2(ull v) {
    float r;
    asm("{\n\t"
        ".reg .f32 lo, hi;\n\t"
        "mov.b64 {lo, hi}, %1;\n\t"
        "add.f32 %0, lo, hi;\n\t"
        "}" : "=f"(r) : "l"(v));
    return r;
}

// ---------------------------------------------------------------------------
// Kernel 1: blocks 1+2. grid (64, 15), block 256. 8 y2 rows per CTA.
// Phase 2: thread owns 4 consecutive channels -> 1 LDS + 1 STG.128 per row.
// ---------------------------------------------------------------------------
__global__ __launch_bounds__(256) void k_front(
    const float* __restrict__ state, const float* __restrict__ k1,
    const float* __restrict__ b1, const float* __restrict__ k2,
    const float* __restrict__ b2)
{
    __shared__ float s_y1[FY1 * C1];   // 6 KB
    const int b   = blockIdx.x;
    const int ty  = blockIdx.y;
    const int tid = threadIdx.x;
    const int t0  = ty * FROWS;        // y2 rows [t0, t0+8)
    const float* st = state + (size_t)b * L0 * C0;

    // ---- y1 rows t0..t0+11 (R15 proven form) ----
    {
        const int c1 = tid & (C1 - 1);
        const int g1 = c1 >> 3;
        float kr[KW];
        const float bb = b1[c1];
        #pragma unroll
        for (int k = 0; k < KW; k++) kr[k] = k1[k * C1 + c1];
        #pragma unroll
        for (int i = (tid >> 7); i < FY1; i += 2) {
            const int t = t0 + i;
            float z = bb;
            #pragma unroll
            for (int k = 0; k < KW; k++)
                z = fmaf(st[(t + k) * C0 + g1], kr[k], z);
            s_y1[i * C1 + c1] = fmaxf(z, 0.f);
        }
    }
    __syncthreads();

    // ---- y2 rows: 4 consecutive channels per thread ----
    {
        const int c2b = tid * 4;          // channels [c2b, c2b+4), all same group
        const int g2  = c2b >> 3;
        float kr[4][KW];
        float bb[4];
        #pragma unroll
        for (int v = 0; v < 4; v++) {
            bb[v] = b2[c2b + v];
            #pragma unroll
            for (int k = 0; k < KW; k++) kr[v][k] = k2[k * C2 + c2b + v];
        }
        float* yout = g_y2 + ((size_t)b * L2N + t0) * C2 + c2b;
        float w0 = s_y1[0 * C1 + g2];
        float w1 = s_y1[1 * C1 + g2];
        float w2 = s_y1[2 * C1 + g2];
        float w3 = s_y1[3 * C1 + g2];
        #pragma unroll
        for (int i = 0; i < FROWS; i++) {
            const float w4 = s_y1[(i + 4) * C1 + g2];
            float4 o;
            #pragma unroll
            for (int v = 0; v < 4; v++) {
                float z = bb[v];
                z = fmaf(w0, kr[v][0], z);
                z = fmaf(w1, kr[v][1], z);
                z = fmaf(w2, kr[v][2], z);
                z = fmaf(w3, kr[v][3], z);
                z = fmaf(w4, kr[v][4], z);
                const float r = fmaxf(z, 0.f);
                if (v == 0) o.x = r;
                else if (v == 1) o.y = r;
                else if (v == 2) o.z = r;
                else o.w = r;
            }
            *(float4*)(yout + (size_t)i * C2) = o;
            w0 = w1; w1 = w2; w2 = w3; w3 = w4;
        }
    }
}

// ---------------------------------------------------------------------------
// Kernel 2: fused block3 + dense (R15 measured-best structure; only relu/hadd
// replaced by fused asm blocks). grid 444, block 256, 3 CTAs/SM.
// ---------------------------------------------------------------------------
__global__ __launch_bounds__(256, 3) void k_back(
    const float* __restrict__ k3, const float* __restrict__ b3,
    const float* __restrict__ W)
{
    const int tid  = threadIdx.x;
    const int lane = tid & 31;
    const int wid  = tid >> 5;
    const int wg   = blockIdx.x * 8 + wid;

    const int cnt   = TPW + (wg < TREM);
    const int start = wg * TPW + (wg < TREM ? wg : TREM);
    const int end   = start + cnt;

    const int fp = lane & 3;     // filter pair within group
    const int gl = lane >> 2;    // group within g8 block

    int uprev = -1;
    ull kr2[KW];       // conv weights, packed filter pair
    ull br2 = 0;       // bias pair
    ull wr2[TT][AD];   // dense weights

    for (int j = start; j < end; j++) {
        const int u    = j >> 3, bc = j & 7;
        const int tblk = u % NTBLK, g8 = u / NTBLK;
        const int g3   = g8 * 8 + gl;
        const int t30  = tblk * TT;
        const int c    = g3 * 8 + fp * 2;   // first of 2 channels this lane owns

        if (u != uprev) {
            uprev = u;
            #pragma unroll
            for (int k = 0; k < KW; k++)
                kr2[k] = *(const ull*)(k3 + k * C3 + c);
            br2 = *(const ull*)(b3 + c);
            #pragma unroll
            for (int i = 0; i < TT; i++) {
                float4 q = *(const float4*)(W + ((size_t)(t30 + i) * C3 + c) * AD);
                wr2[i][0] = pack2(q.x, q.z);   // action 0: (w[c], w[c+1])
                wr2[i][1] = pack2(q.y, q.w);   // action 1
            }
        }

        const float* ytask = g_y2 + ((size_t)(bc * BPT) * L2N + t30) * C2 + g3;
        ull acc[BPT / 2];

        // prime: load batch 0 rows
        float yv[TT + 4];
        #pragma unroll
        for (int r = 0; r < TT + 4; r++) yv[r] = ytask[(size_t)r * C2];

        #pragma unroll
        for (int half = 0; half < 2; half++) {
            #pragma unroll
            for (int q = 0; q < BPT / 2; q++) {
                const int bb = half * (BPT / 2) + q;
                // ---- prefetch next batch while computing this one ----
                float yn[TT + 4];
                if (bb + 1 < BPT) {
                    const float* yp = ytask + (size_t)(bb + 1) * L2N * C2;
                    #pragma unroll
                    for (int r = 0; r < TT + 4; r++) yn[r] = yp[(size_t)r * C2];
                }

                ull yv2[TT + 4];
                #pragma unroll
                for (int r = 0; r < TT + 4; r++) yv2[r] = pack2(yv[r], yv[r]);

                ull a0p = 0ull, a1p = 0ull;
                #pragma unroll
                for (int i = 0; i < TT; i++) {
                    ull z2 = br2;
                    #pragma unroll
                    for (int k = 0; k < KW; k++)
                        z2 = ffma2(yv2[i + k], kr2[k], z2);
                    const ull v2 = relu2(z2);
                    a0p = ffma2(v2, wr2[i][0], a0p);
                    a1p = ffma2(v2, wr2[i][1], a1p);
                }
                // fold filter-pair halves -> packed (act0, act1)
                acc[q] = pack2(hadd2(a0p), hadd2(a1p));

                if (bb + 1 < BPT) {
                    #pragma unroll
                    for (int r = 0; r < TT + 4; r++) yv[r] = yn[r];
                }
            }

            // ---- quad reduction for this half (2 interleaved shuffle steps) ----
            #pragma unroll
            for (int off = 1; off <= 2; off <<= 1) {
                #pragma unroll
                for (int q = 0; q < BPT / 2; q++)
                    acc[q] = add2(acc[q], __shfl_xor_sync(0xffffffffu, acc[q], off));
            }
            if (fp == 0) {
                #pragma unroll
                for (int q = 0; q < BPT / 2; q++) {
                    const int b = bc * BPT + half * (BPT / 2) + q;
                    float r0, r1;
                    unpack2(acc[q], r0, r1);
                    float2 res; res.x = r0; res.y = r1;
                    *(float2*)(g_part2 + (((size_t)b * NU + u) * 8 + gl) * AD) = res;
                }
            }
        }
    }
}

// ---------------------------------------------------------------------------
// Kernel 3: per-batch reduce of NU*8 float2 partials, bias + tanh.
// grid 64 (one block per batch), block 256.
// ---------------------------------------------------------------------------
__global__ __launch_bounds__(256) void k_out(
    const float* __restrict__ bd, float* __restrict__ out)
{
    __shared__ float s0[8], s1[8];
    const int b   = blockIdx.x;
    const int tid = threadIdx.x;
    const float2* p = (const float2*)(g_part2 + (size_t)b * NU * 8 * AD);
    float v0 = 0.f, v1 = 0.f;
    for (int i = tid; i < NU * 8; i += 256) {
        float2 q = p[i];
        v0 += q.x; v1 += q.y;
    }
    #pragma unroll
    for (int off = 16; off; off >>= 1) {
        v0 += __shfl_xor_sync(0xffffffffu, v0, off);
        v1 += __shfl_xor_sync(0xffffffffu, v1, off);
    }
    if ((tid & 31) == 0) { s0[tid >> 5] = v0; s1[tid >> 5] = v1; }
    __syncthreads();
    if (tid == 0) {
        float a0 = 0.f, a1 = 0.f;
        #pragma unroll
        for (int w = 0; w < 8; w++) { a0 += s0[w]; a1 += s1[w]; }
        out[b * AD + 0] = tanhf(a0 + bd[0]);
        out[b * AD + 1] = tanhf(a1 + bd[1]);
    }
}

extern "C" void kernel_launch(void* const* d_in, const int* in_sizes, int n_in,
                              void* d_out, int out_size) {
    (void)in_sizes; (void)n_in; (void)out_size;
    const float* state = (const float*)d_in[0];
    const float* k1    = (const float*)d_in[1];
    const float* b1    = (const float*)d_in[2];
    const float* k2    = (const float*)d_in[3];
    const float* b2    = (const float*)d_in[4];
    const float* k3    = (const float*)d_in[5];
    const float* b3    = (const float*)d_in[6];
    const float* W     = (const float*)d_in[7];
    const float* bd    = (const float*)d_in[8];
    float* out = (float*)d_out;

    k_front<<<dim3(BATCH, L2N / FROWS), 256>>>(state, k1, b1, k2, b2);
    k_back <<<GRID_BACK, 256>>>(k3, b3, W);
    k_out  <<<BATCH, 256>>>(bd, out);
}